// round 1
// baseline (speedup 1.0000x reference)
#include <cuda_runtime.h>
#include <math.h>

#define BATCH 4096
#define HID   256
#define VOC   64
#define EMBD  64
#define ZDIM  128
#define NL    3
#define TT    120   // sequence length; TT-1 = 119 decode steps

// Persistent state (device globals -- no allocation allowed).
// g_h[layer][parity][batch][hid], double-buffered by step parity.
__device__ float g_h[NL][2][BATCH][HID];
// Embedded current token vector per row (input x for layer 0).
__device__ float g_x0[BATCH][EMBD];

__device__ __forceinline__ float sigmoidf_(float x) {
    return 1.0f / (1.0f + expf(-x));
}

// ---------------------------------------------------------------------------
// Fused GEMM + GRU cell for one layer.
// gates[b, g*256+u] = sum_k x[b,k]*wih[g*256+u,k] + sum_k h[b,k]*whh[g*256+u,k]
// then PyTorch GRUCell elementwise math.
// Block tile: 64 batch rows x 64 hidden units (=> 192 gate columns).
// Shared tiles are stored transposed [k][row/col] so the inner loop is
// 4x LDS.128 per 48 FFMA.
// ---------------------------------------------------------------------------
template <int KIN>
__global__ void __launch_bounds__(256, 2) gru_layer_kernel(
    int layer, int p,
    const float* __restrict__ wih, const float* __restrict__ whh,
    const float* __restrict__ bih, const float* __restrict__ bhh)
{
    constexpr int BM = 64;   // batch rows per block
    constexpr int BU = 64;   // hidden units per block (3 gates each)
    constexpr int KC = 32;   // k chunk

    __shared__ float As[KC][BM + 4];          // [k][row]
    __shared__ float Ws[KC][3 * BU + 4];      // [k][gate*64 + u]

    const float* xin  = (layer == 0) ? &g_x0[0][0] : &g_h[layer - 1][p ^ 1][0][0];
    const float* hin  = &g_h[layer][p][0][0];
    float*       hout = &g_h[layer][p ^ 1][0][0];

    const int tid = threadIdx.x;
    const int tx  = tid & 15;     // -> 4 units
    const int ty  = tid >> 4;     // -> 4 rows
    const int r0  = blockIdx.x * BM;
    const int u0  = blockIdx.y * BU;

    float accR[4][4]  = {};   // ir+hr accumulated across both passes
    float accZ[4][4]  = {};   // iz+hz
    float accNi[4][4] = {};   // inn
    float accNh[4][4] = {};   // hn

    // ----- pass 1: x @ wih^T -----
    for (int k0 = 0; k0 < KIN; k0 += KC) {
        __syncthreads();
#pragma unroll
        for (int it = 0; it < 2; ++it) {
            int idx = tid + 256 * it;                 // 512 float4 loads
            int row = idx >> 3, k4 = (idx & 7) * 4;
            float4 v = *(const float4*)&xin[(size_t)(r0 + row) * KIN + k0 + k4];
            As[k4][row] = v.x; As[k4 + 1][row] = v.y;
            As[k4 + 2][row] = v.z; As[k4 + 3][row] = v.w;
        }
#pragma unroll
        for (int it = 0; it < 6; ++it) {
            int idx = tid + 256 * it;                 // 1536 float4 loads
            int c = idx >> 3, k4 = (idx & 7) * 4;
            int g = c >> 6, u = c & 63;
            float4 v = *(const float4*)&wih[(size_t)(g * HID + u0 + u) * KIN + k0 + k4];
            Ws[k4][c] = v.x; Ws[k4 + 1][c] = v.y;
            Ws[k4 + 2][c] = v.z; Ws[k4 + 3][c] = v.w;
        }
        __syncthreads();
#pragma unroll
        for (int k = 0; k < KC; ++k) {
            float4 a4 = *(const float4*)&As[k][ty * 4];
            float4 w0 = *(const float4*)&Ws[k][tx * 4];
            float4 w1 = *(const float4*)&Ws[k][BU + tx * 4];
            float4 w2 = *(const float4*)&Ws[k][2 * BU + tx * 4];
            float a[4]  = {a4.x, a4.y, a4.z, a4.w};
            float wr[4] = {w0.x, w0.y, w0.z, w0.w};
            float wz[4] = {w1.x, w1.y, w1.z, w1.w};
            float wn[4] = {w2.x, w2.y, w2.z, w2.w};
#pragma unroll
            for (int i = 0; i < 4; ++i)
#pragma unroll
                for (int j = 0; j < 4; ++j) {
                    accR[i][j]  += a[i] * wr[j];
                    accZ[i][j]  += a[i] * wz[j];
                    accNi[i][j] += a[i] * wn[j];
                }
        }
    }

    // ----- pass 2: h @ whh^T -----
    for (int k0 = 0; k0 < HID; k0 += KC) {
        __syncthreads();
#pragma unroll
        for (int it = 0; it < 2; ++it) {
            int idx = tid + 256 * it;
            int row = idx >> 3, k4 = (idx & 7) * 4;
            float4 v = *(const float4*)&hin[(size_t)(r0 + row) * HID + k0 + k4];
            As[k4][row] = v.x; As[k4 + 1][row] = v.y;
            As[k4 + 2][row] = v.z; As[k4 + 3][row] = v.w;
        }
#pragma unroll
        for (int it = 0; it < 6; ++it) {
            int idx = tid + 256 * it;
            int c = idx >> 3, k4 = (idx & 7) * 4;
            int g = c >> 6, u = c & 63;
            float4 v = *(const float4*)&whh[(size_t)(g * HID + u0 + u) * HID + k0 + k4];
            Ws[k4][c] = v.x; Ws[k4 + 1][c] = v.y;
            Ws[k4 + 2][c] = v.z; Ws[k4 + 3][c] = v.w;
        }
        __syncthreads();
#pragma unroll
        for (int k = 0; k < KC; ++k) {
            float4 a4 = *(const float4*)&As[k][ty * 4];
            float4 w0 = *(const float4*)&Ws[k][tx * 4];
            float4 w1 = *(const float4*)&Ws[k][BU + tx * 4];
            float4 w2 = *(const float4*)&Ws[k][2 * BU + tx * 4];
            float a[4]  = {a4.x, a4.y, a4.z, a4.w};
            float wr[4] = {w0.x, w0.y, w0.z, w0.w};
            float wz[4] = {w1.x, w1.y, w1.z, w1.w};
            float wn[4] = {w2.x, w2.y, w2.z, w2.w};
#pragma unroll
            for (int i = 0; i < 4; ++i)
#pragma unroll
                for (int j = 0; j < 4; ++j) {
                    accR[i][j]  += a[i] * wr[j];
                    accZ[i][j]  += a[i] * wz[j];
                    accNh[i][j] += a[i] * wn[j];
                }
        }
    }

    // ----- GRU elementwise combine (PyTorch GRUCell math) -----
#pragma unroll
    for (int j = 0; j < 4; ++j) {
        int u = u0 + tx * 4 + j;
        float br  = bih[u] + bhh[u];
        float bz  = bih[HID + u] + bhh[HID + u];
        float bni = bih[2 * HID + u];
        float bnh = bhh[2 * HID + u];
#pragma unroll
        for (int i = 0; i < 4; ++i) {
            int r = r0 + ty * 4 + i;
            float hold = hin[(size_t)r * HID + u];
            float rg = sigmoidf_(accR[i][j] + br);
            float zg = sigmoidf_(accZ[i][j] + bz);
            float ng = tanhf(accNi[i][j] + bni + rg * (accNh[i][j] + bnh));
            hout[(size_t)r * HID + u] = (1.0f - zg) * ng + zg * hold;
        }
    }
}

// ---------------------------------------------------------------------------
// Output: logits = h2 @ out_w^T + out_b, write logits, argmax (first-max
// tie-break like jnp.argmax), gather emb[token] into g_x0 for next step.
// One warp per batch row; lane handles vocab {lane, lane+32}.
// ---------------------------------------------------------------------------
__global__ void __launch_bounds__(256) out_kernel(
    int t, int p,
    const float* __restrict__ ow, const float* __restrict__ ob,
    const float* __restrict__ emb, float* __restrict__ out)
{
    __shared__ float hs[8][HID];
    const int w    = threadIdx.x >> 5;
    const int lane = threadIdx.x & 31;
    const int b    = blockIdx.x * 8 + w;

    const float* h2 = &g_h[2][p ^ 1][b][0];
    *(float4*)&hs[w][lane * 4]       = *(const float4*)&h2[lane * 4];
    *(float4*)&hs[w][128 + lane * 4] = *(const float4*)&h2[128 + lane * 4];
    __syncwarp();

    const int v1 = lane, v2 = lane + 32;
    float acc1 = ob[v1], acc2 = ob[v2];
#pragma unroll
    for (int k = 0; k < HID; k += 4) {
        float4 h4  = *(const float4*)&hs[w][k];
        float4 w14 = *(const float4*)&ow[(size_t)v1 * HID + k];
        float4 w24 = *(const float4*)&ow[(size_t)v2 * HID + k];
        acc1 += h4.x * w14.x + h4.y * w14.y + h4.z * w14.z + h4.w * w14.w;
        acc2 += h4.x * w24.x + h4.y * w24.y + h4.z * w24.z + h4.w * w24.w;
    }

    size_t off = ((size_t)b * (TT - 1) + t) * VOC;
    out[off + v1] = acc1;
    out[off + v2] = acc2;

    // argmax with first-index tie-break
    float bv = acc1; int bi = v1;
    if (acc2 > bv) { bv = acc2; bi = v2; }
#pragma unroll
    for (int o = 16; o; o >>= 1) {
        float ovv = __shfl_xor_sync(0xffffffffu, bv, o);
        int   oi  = __shfl_xor_sync(0xffffffffu, bi, o);
        if (ovv > bv || (ovv == bv && oi < bi)) { bv = ovv; bi = oi; }
    }

    // gather embedding row of winning token for next step
    g_x0[b][lane]      = emb[(size_t)bi * EMBD + lane];
    g_x0[b][lane + 32] = emb[(size_t)bi * EMBD + lane + 32];
}

// ---------------------------------------------------------------------------
// h0 = tanh(z @ z2h_w^T + z2h_b), scattered into g_h[l][0][b][u]
// (column j of the 768-wide result -> layer j>>8, unit j&255).
// ---------------------------------------------------------------------------
__global__ void __launch_bounds__(256) init_h_kernel(
    const float* __restrict__ z, const float* __restrict__ zw,
    const float* __restrict__ zb)
{
    constexpr int BM = 64, BN = 64, KC = 32;
    __shared__ float As[KC][BM + 4];
    __shared__ float Ws[KC][BN + 4];

    const int tid = threadIdx.x, tx = tid & 15, ty = tid >> 4;
    const int r0 = blockIdx.x * BM, j0 = blockIdx.y * BN;

    float acc[4][4] = {};
    for (int k0 = 0; k0 < ZDIM; k0 += KC) {
        __syncthreads();
#pragma unroll
        for (int it = 0; it < 2; ++it) {
            int idx = tid + 256 * it;
            int row = idx >> 3, k4 = (idx & 7) * 4;
            float4 v = *(const float4*)&z[(size_t)(r0 + row) * ZDIM + k0 + k4];
            As[k4][row] = v.x; As[k4 + 1][row] = v.y;
            As[k4 + 2][row] = v.z; As[k4 + 3][row] = v.w;
        }
#pragma unroll
        for (int it = 0; it < 2; ++it) {
            int idx = tid + 256 * it;
            int c = idx >> 3, k4 = (idx & 7) * 4;
            float4 v = *(const float4*)&zw[(size_t)(j0 + c) * ZDIM + k0 + k4];
            Ws[k4][c] = v.x; Ws[k4 + 1][c] = v.y;
            Ws[k4 + 2][c] = v.z; Ws[k4 + 3][c] = v.w;
        }
        __syncthreads();
#pragma unroll
        for (int k = 0; k < KC; ++k) {
            float4 a4 = *(const float4*)&As[k][ty * 4];
            float4 w4 = *(const float4*)&Ws[k][tx * 4];
            float a[4]  = {a4.x, a4.y, a4.z, a4.w};
            float wv[4] = {w4.x, w4.y, w4.z, w4.w};
#pragma unroll
            for (int i = 0; i < 4; ++i)
#pragma unroll
                for (int j = 0; j < 4; ++j) acc[i][j] += a[i] * wv[j];
        }
    }
#pragma unroll
    for (int j = 0; j < 4; ++j) {
        int jj = j0 + tx * 4 + j;
        int l = jj >> 8, u = jj & 255;
        float bb = zb[jj];
#pragma unroll
        for (int i = 0; i < 4; ++i) {
            int r = r0 + ty * 4 + i;
            g_h[l][0][r][u] = tanhf(acc[i][j] + bb);
        }
    }
}

// g_x0[b][:] = emb[1][:]  (start token = 1)
__global__ void init_x_kernel(const float* __restrict__ emb)
{
    int i = blockIdx.x * blockDim.x + threadIdx.x;
    if (i < BATCH * EMBD) {
        ((float*)g_x0)[i] = emb[EMBD + (i & (EMBD - 1))];
    }
}

// ---------------------------------------------------------------------------
extern "C" void kernel_launch(void* const* d_in, const int* in_sizes, int n_in,
                              void* d_out, int out_size)
{
    const float* z     = (const float*)d_in[0];
    const float* emb   = (const float*)d_in[1];
    const float* z2h_w = (const float*)d_in[2];
    const float* z2h_b = (const float*)d_in[3];
    const float* out_w = (const float*)d_in[4];
    const float* out_b = (const float*)d_in[5];
    const float* wih[NL] = {(const float*)d_in[6],  (const float*)d_in[10], (const float*)d_in[14]};
    const float* whh[NL] = {(const float*)d_in[7],  (const float*)d_in[11], (const float*)d_in[15]};
    const float* bih[NL] = {(const float*)d_in[8],  (const float*)d_in[12], (const float*)d_in[16]};
    const float* bhh[NL] = {(const float*)d_in[9],  (const float*)d_in[13], (const float*)d_in[17]};
    float* out = (float*)d_out;

    init_h_kernel<<<dim3(BATCH / 64, 768 / 64), 256>>>(z, z2h_w, z2h_b);
    init_x_kernel<<<(BATCH * EMBD + 255) / 256, 256>>>(emb);

    dim3 lgrid(BATCH / 64, HID / 64);   // 64 x 4 blocks
    for (int t = 0; t < TT - 1; ++t) {
        int p = t & 1;
        gru_layer_kernel<EMBD><<<lgrid, 256>>>(0, p, wih[0], whh[0], bih[0], bhh[0]);
        gru_layer_kernel<HID ><<<lgrid, 256>>>(1, p, wih[1], whh[1], bih[1], bhh[1]);
        gru_layer_kernel<HID ><<<lgrid, 256>>>(2, p, wih[2], whh[2], bih[2], bhh[2]);
        out_kernel<<<BATCH / 8, 256>>>(t, p, out_w, out_b, emb, out);
    }
}

// round 2
// speedup vs baseline: 1.0272x; 1.0272x over previous
#include <cuda_runtime.h>
#include <math.h>

#define BATCH 4096
#define HID   256
#define VOC   64
#define EMBD  64
#define ZDIM  128
#define NL    3
#define TT    120   // sequence length; TT-1 = 119 decode steps

// Persistent state (device globals -- no allocation allowed).
__device__ float g_h[NL][2][BATCH][HID];   // double-buffered by step parity
__device__ float g_x0[BATCH][EMBD];        // embedded current token

__device__ __forceinline__ float sigmoidf_(float x) {
    return 1.0f / (1.0f + expf(-x));
}

__device__ __forceinline__ unsigned long long dup_f32(float v) {
    unsigned long long d;
    asm("mov.b64 %0, {%1, %1};" : "=l"(d) : "r"(__float_as_uint(v)));
    return d;
}
__device__ __forceinline__ void ffma2(unsigned long long& acc,
                                      unsigned long long a,
                                      unsigned long long b) {
    asm("fma.rn.f32x2 %0, %1, %2, %0;" : "+l"(acc) : "l"(a), "l"(b));
}
__device__ __forceinline__ float lo32(unsigned long long v) {
    return __uint_as_float((unsigned)(v & 0xffffffffULL));
}
__device__ __forceinline__ float hi32(unsigned long long v) {
    return __uint_as_float((unsigned)(v >> 32));
}

// ---------------------------------------------------------------------------
// Fused GEMM + GRU cell, packed-f32x2 inner loop.
// Block: 128 threads (tx=16 -> 12 gate cols, ty=8 -> 8 rows).
// Tile: 64 batch rows x 64 hidden units (192 gate columns).
// ---------------------------------------------------------------------------
template <int KIN>
__global__ void __launch_bounds__(128, 2) gru_layer_kernel(
    int layer, int p,
    const float* __restrict__ wih, const float* __restrict__ whh,
    const float* __restrict__ bih, const float* __restrict__ bhh)
{
    constexpr int BM = 64;
    constexpr int BU = 64;
    constexpr int KC = 32;

    __shared__ float As[KC][BM + 4];          // [k][row]   (68 floats/row: 16B-mult)
    __shared__ float Ws[KC][3 * BU + 4];      // [k][col]   (196 floats/row: 16B-mult)

    const float* xin  = (layer == 0) ? &g_x0[0][0] : &g_h[layer - 1][p ^ 1][0][0];
    const float* hin  = &g_h[layer][p][0][0];
    float*       hout = &g_h[layer][p ^ 1][0][0];

    const int tid = threadIdx.x;
    const int tx  = tid & 15;     // 12 gate cols: per gate, cols tx*4..tx*4+3
    const int ty  = tid >> 4;     // 8 rows: ty*8..ty*8+7
    const int r0  = blockIdx.x * BM;
    const int u0  = blockIdx.y * BU;

    // acc[i][j]: j = gate*2 + pair; pass1 accumulates R,Z,Ni (j 0..5),
    // pass2 accumulates R,Z into j 0..3 and Nh into accNh.
    unsigned long long acc[8][6];
    unsigned long long accNh[8][2];
#pragma unroll
    for (int i = 0; i < 8; ++i) {
#pragma unroll
        for (int j = 0; j < 6; ++j) acc[i][j] = 0ULL;
        accNh[i][0] = accNh[i][1] = 0ULL;
    }

    // ================= pass 1: x @ wih^T =================
    for (int k0 = 0; k0 < KIN; k0 += KC) {
        __syncthreads();
#pragma unroll
        for (int it = 0; it < 4; ++it) {            // 512 float4
            int idx = tid + 128 * it;
            int row = idx >> 3, k4 = (idx & 7) * 4;
            float4 v = *(const float4*)&xin[(size_t)(r0 + row) * KIN + k0 + k4];
            As[k4][row] = v.x; As[k4 + 1][row] = v.y;
            As[k4 + 2][row] = v.z; As[k4 + 3][row] = v.w;
        }
#pragma unroll
        for (int it = 0; it < 12; ++it) {           // 1536 float4
            int idx = tid + 128 * it;
            int c = idx >> 3, k4 = (idx & 7) * 4;
            int g = c >> 6, u = c & 63;
            float4 v = *(const float4*)&wih[(size_t)(g * HID + u0 + u) * KIN + k0 + k4];
            Ws[k4][c] = v.x; Ws[k4 + 1][c] = v.y;
            Ws[k4 + 2][c] = v.z; Ws[k4 + 3][c] = v.w;
        }
        __syncthreads();
#pragma unroll
        for (int k = 0; k < KC; ++k) {
            float4 a0 = *(const float4*)&As[k][ty * 8];
            float4 a1 = *(const float4*)&As[k][ty * 8 + 4];
            ulonglong2 w0 = *(const ulonglong2*)&Ws[k][tx * 4];
            ulonglong2 w1 = *(const ulonglong2*)&Ws[k][BU + tx * 4];
            ulonglong2 w2 = *(const ulonglong2*)&Ws[k][2 * BU + tx * 4];
            float a[8] = {a0.x, a0.y, a0.z, a0.w, a1.x, a1.y, a1.z, a1.w};
#pragma unroll
            for (int i = 0; i < 8; ++i) {
                unsigned long long ad = dup_f32(a[i]);
                ffma2(acc[i][0], ad, w0.x); ffma2(acc[i][1], ad, w0.y);
                ffma2(acc[i][2], ad, w1.x); ffma2(acc[i][3], ad, w1.y);
                ffma2(acc[i][4], ad, w2.x); ffma2(acc[i][5], ad, w2.y);
            }
        }
    }

    // ================= pass 2: h @ whh^T =================
    for (int k0 = 0; k0 < HID; k0 += KC) {
        __syncthreads();
#pragma unroll
        for (int it = 0; it < 4; ++it) {
            int idx = tid + 128 * it;
            int row = idx >> 3, k4 = (idx & 7) * 4;
            float4 v = *(const float4*)&hin[(size_t)(r0 + row) * HID + k0 + k4];
            As[k4][row] = v.x; As[k4 + 1][row] = v.y;
            As[k4 + 2][row] = v.z; As[k4 + 3][row] = v.w;
        }
#pragma unroll
        for (int it = 0; it < 12; ++it) {
            int idx = tid + 128 * it;
            int c = idx >> 3, k4 = (idx & 7) * 4;
            int g = c >> 6, u = c & 63;
            float4 v = *(const float4*)&whh[(size_t)(g * HID + u0 + u) * HID + k0 + k4];
            Ws[k4][c] = v.x; Ws[k4 + 1][c] = v.y;
            Ws[k4 + 2][c] = v.z; Ws[k4 + 3][c] = v.w;
        }
        __syncthreads();
#pragma unroll
        for (int k = 0; k < KC; ++k) {
            float4 a0 = *(const float4*)&As[k][ty * 8];
            float4 a1 = *(const float4*)&As[k][ty * 8 + 4];
            ulonglong2 w0 = *(const ulonglong2*)&Ws[k][tx * 4];
            ulonglong2 w1 = *(const ulonglong2*)&Ws[k][BU + tx * 4];
            ulonglong2 w2 = *(const ulonglong2*)&Ws[k][2 * BU + tx * 4];
            float a[8] = {a0.x, a0.y, a0.z, a0.w, a1.x, a1.y, a1.z, a1.w};
#pragma unroll
            for (int i = 0; i < 8; ++i) {
                unsigned long long ad = dup_f32(a[i]);
                ffma2(acc[i][0], ad, w0.x); ffma2(acc[i][1], ad, w0.y);
                ffma2(acc[i][2], ad, w1.x); ffma2(acc[i][3], ad, w1.y);
                ffma2(accNh[i][0], ad, w2.x); ffma2(accNh[i][1], ad, w2.y);
            }
        }
    }

    // ================= GRU elementwise combine =================
#pragma unroll
    for (int pp = 0; pp < 2; ++pp) {
#pragma unroll
        for (int half = 0; half < 2; ++half) {
            int u = u0 + tx * 4 + pp * 2 + half;
            float br  = bih[u] + bhh[u];
            float bz  = bih[HID + u] + bhh[HID + u];
            float bni = bih[2 * HID + u];
            float bnh = bhh[2 * HID + u];
#pragma unroll
            for (int i = 0; i < 8; ++i) {
                int r = r0 + ty * 8 + i;
                float vR  = half ? hi32(acc[i][pp])     : lo32(acc[i][pp]);
                float vZ  = half ? hi32(acc[i][2 + pp]) : lo32(acc[i][2 + pp]);
                float vNi = half ? hi32(acc[i][4 + pp]) : lo32(acc[i][4 + pp]);
                float vNh = half ? hi32(accNh[i][pp])   : lo32(accNh[i][pp]);
                float hold = hin[(size_t)r * HID + u];
                float rg = sigmoidf_(vR + br);
                float zg = sigmoidf_(vZ + bz);
                float ng = tanhf(vNi + bni + rg * (vNh + bnh));
                hout[(size_t)r * HID + u] = (1.0f - zg) * ng + zg * hold;
            }
        }
    }
}

// ---------------------------------------------------------------------------
// Output: logits = h2 @ out_w^T + out_b, argmax (first-index tie-break),
// embedding gather for next step. One warp per row.
// ---------------------------------------------------------------------------
__global__ void __launch_bounds__(256) out_kernel(
    int t, int p,
    const float* __restrict__ ow, const float* __restrict__ ob,
    const float* __restrict__ emb, float* __restrict__ out)
{
    __shared__ float hs[8][HID];
    const int w    = threadIdx.x >> 5;
    const int lane = threadIdx.x & 31;
    const int b    = blockIdx.x * 8 + w;

    const float* h2 = &g_h[2][p ^ 1][b][0];
    *(float4*)&hs[w][lane * 4]       = *(const float4*)&h2[lane * 4];
    *(float4*)&hs[w][128 + lane * 4] = *(const float4*)&h2[128 + lane * 4];
    __syncwarp();

    const int v1 = lane, v2 = lane + 32;
    float acc1 = ob[v1], acc2 = ob[v2];
#pragma unroll
    for (int k = 0; k < HID; k += 4) {
        float4 h4  = *(const float4*)&hs[w][k];
        float4 w14 = *(const float4*)&ow[(size_t)v1 * HID + k];
        float4 w24 = *(const float4*)&ow[(size_t)v2 * HID + k];
        acc1 += h4.x * w14.x + h4.y * w14.y + h4.z * w14.z + h4.w * w14.w;
        acc2 += h4.x * w24.x + h4.y * w24.y + h4.z * w24.z + h4.w * w24.w;
    }

    size_t off = ((size_t)b * (TT - 1) + t) * VOC;
    out[off + v1] = acc1;
    out[off + v2] = acc2;

    float bv = acc1; int bi = v1;
    if (acc2 > bv) { bv = acc2; bi = v2; }
#pragma unroll
    for (int o = 16; o; o >>= 1) {
        float ovv = __shfl_xor_sync(0xffffffffu, bv, o);
        int   oi  = __shfl_xor_sync(0xffffffffu, bi, o);
        if (ovv > bv || (ovv == bv && oi < bi)) { bv = ovv; bi = oi; }
    }

    g_x0[b][lane]      = emb[(size_t)bi * EMBD + lane];
    g_x0[b][lane + 32] = emb[(size_t)bi * EMBD + lane + 32];
}

// ---------------------------------------------------------------------------
// h0 = tanh(z @ z2h_w^T + z2h_b) scattered into g_h[l][0][b][u].
// ---------------------------------------------------------------------------
__global__ void __launch_bounds__(256) init_h_kernel(
    const float* __restrict__ z, const float* __restrict__ zw,
    const float* __restrict__ zb)
{
    constexpr int BM = 64, BN = 64, KC = 32;
    __shared__ float As[KC][BM + 4];
    __shared__ float Ws[KC][BN + 4];

    const int tid = threadIdx.x, tx = tid & 15, ty = tid >> 4;
    const int r0 = blockIdx.x * BM, j0 = blockIdx.y * BN;

    float acc[4][4] = {};
    for (int k0 = 0; k0 < ZDIM; k0 += KC) {
        __syncthreads();
#pragma unroll
        for (int it = 0; it < 2; ++it) {
            int idx = tid + 256 * it;
            int row = idx >> 3, k4 = (idx & 7) * 4;
            float4 v = *(const float4*)&z[(size_t)(r0 + row) * ZDIM + k0 + k4];
            As[k4][row] = v.x; As[k4 + 1][row] = v.y;
            As[k4 + 2][row] = v.z; As[k4 + 3][row] = v.w;
        }
#pragma unroll
        for (int it = 0; it < 2; ++it) {
            int idx = tid + 256 * it;
            int c = idx >> 3, k4 = (idx & 7) * 4;
            float4 v = *(const float4*)&zw[(size_t)(j0 + c) * ZDIM + k0 + k4];
            Ws[k4][c] = v.x; Ws[k4 + 1][c] = v.y;
            Ws[k4 + 2][c] = v.z; Ws[k4 + 3][c] = v.w;
        }
        __syncthreads();
#pragma unroll
        for (int k = 0; k < KC; ++k) {
            float4 a4 = *(const float4*)&As[k][ty * 4];
            float4 w4 = *(const float4*)&Ws[k][tx * 4];
            float a[4]  = {a4.x, a4.y, a4.z, a4.w};
            float wv[4] = {w4.x, w4.y, w4.z, w4.w};
#pragma unroll
            for (int i = 0; i < 4; ++i)
#pragma unroll
                for (int j = 0; j < 4; ++j) acc[i][j] += a[i] * wv[j];
        }
    }
#pragma unroll
    for (int j = 0; j < 4; ++j) {
        int jj = j0 + tx * 4 + j;
        int l = jj >> 8, u = jj & 255;
        float bb = zb[jj];
#pragma unroll
        for (int i = 0; i < 4; ++i) {
            int r = r0 + ty * 4 + i;
            g_h[l][0][r][u] = tanhf(acc[i][j] + bb);
        }
    }
}

// g_x0[b][:] = emb[1][:]  (start token = 1)
__global__ void init_x_kernel(const float* __restrict__ emb)
{
    int i = blockIdx.x * blockDim.x + threadIdx.x;
    if (i < BATCH * EMBD) {
        ((float*)g_x0)[i] = emb[EMBD + (i & (EMBD - 1))];
    }
}

// ---------------------------------------------------------------------------
extern "C" void kernel_launch(void* const* d_in, const int* in_sizes, int n_in,
                              void* d_out, int out_size)
{
    const float* z     = (const float*)d_in[0];
    const float* emb   = (const float*)d_in[1];
    const float* z2h_w = (const float*)d_in[2];
    const float* z2h_b = (const float*)d_in[3];
    const float* out_w = (const float*)d_in[4];
    const float* out_b = (const float*)d_in[5];
    const float* wih[NL] = {(const float*)d_in[6],  (const float*)d_in[10], (const float*)d_in[14]};
    const float* whh[NL] = {(const float*)d_in[7],  (const float*)d_in[11], (const float*)d_in[15]};
    const float* bih[NL] = {(const float*)d_in[8],  (const float*)d_in[12], (const float*)d_in[16]};
    const float* bhh[NL] = {(const float*)d_in[9],  (const float*)d_in[13], (const float*)d_in[17]};
    float* out = (float*)d_out;

    init_h_kernel<<<dim3(BATCH / 64, 768 / 64), 256>>>(z, z2h_w, z2h_b);
    init_x_kernel<<<(BATCH * EMBD + 255) / 256, 256>>>(emb);

    dim3 lgrid(BATCH / 64, HID / 64);   // 64 x 4 = 256 blocks
    for (int t = 0; t < TT - 1; ++t) {
        int p = t & 1;
        gru_layer_kernel<EMBD><<<lgrid, 128>>>(0, p, wih[0], whh[0], bih[0], bhh[0]);
        gru_layer_kernel<HID ><<<lgrid, 128>>>(1, p, wih[1], whh[1], bih[1], bhh[1]);
        gru_layer_kernel<HID ><<<lgrid, 128>>>(2, p, wih[2], whh[2], bih[2], bhh[2]);
        out_kernel<<<BATCH / 8, 256>>>(t, p, out_w, out_b, emb, out);
    }
}

// round 3
// speedup vs baseline: 1.0310x; 1.0037x over previous
#include <cuda_runtime.h>
#include <math.h>

#define BATCH 4096
#define HID   256
#define VOC   64
#define EMBD  64
#define ZDIM  128
#define NL    3
#define TT    120   // sequence length; TT-1 = 119 decode steps

// Persistent state (device globals -- no allocation allowed).
__device__ float g_h[NL][2][BATCH][HID];   // double-buffered by step parity
__device__ float g_x0[BATCH][EMBD];        // embedded current token

__device__ __forceinline__ float sigmoidf_(float x) {
    return 1.0f / (1.0f + expf(-x));
}

__device__ __forceinline__ unsigned long long dup_f32(float v) {
    unsigned long long d;
    asm("mov.b64 %0, {%1, %1};" : "=l"(d) : "r"(__float_as_uint(v)));
    return d;
}
__device__ __forceinline__ void ffma2(unsigned long long& acc,
                                      unsigned long long a,
                                      unsigned long long b) {
    asm("fma.rn.f32x2 %0, %1, %2, %0;" : "+l"(acc) : "l"(a), "l"(b));
}
__device__ __forceinline__ float lo32(unsigned long long v) {
    return __uint_as_float((unsigned)(v & 0xffffffffULL));
}
__device__ __forceinline__ float hi32(unsigned long long v) {
    return __uint_as_float((unsigned)(v >> 32));
}

// ---------------------------------------------------------------------------
// Fused GEMM + GRU cell, packed-f32x2 inner loop.
// Block: 128 threads (tx=16 -> 12 gate cols, ty=8 -> 8 rows).
// Tile: 64 batch rows x 64 hidden units (192 gate columns).
// ---------------------------------------------------------------------------
template <int KIN>
__global__ void __launch_bounds__(128, 2) gru_layer_kernel(
    int layer, int p,
    const float* __restrict__ wih, const float* __restrict__ whh,
    const float* __restrict__ bih, const float* __restrict__ bhh)
{
    constexpr int BM = 64;
    constexpr int BU = 64;
    constexpr int KC = 32;

    __shared__ float As[KC][BM + 4];          // [k][row]   (68 floats/row: 16B-mult)
    __shared__ float Ws[KC][3 * BU + 4];      // [k][col]   (196 floats/row: 16B-mult)

    const float* xin  = (layer == 0) ? &g_x0[0][0] : &g_h[layer - 1][p ^ 1][0][0];
    const float* hin  = &g_h[layer][p][0][0];
    float*       hout = &g_h[layer][p ^ 1][0][0];

    const int tid = threadIdx.x;
    const int tx  = tid & 15;     // 12 gate cols: per gate, cols tx*4..tx*4+3
    const int ty  = tid >> 4;     // 8 rows: ty*8..ty*8+7
    const int r0  = blockIdx.x * BM;
    const int u0  = blockIdx.y * BU;

    // acc[i][j]: j = gate*2 + pair; pass1 accumulates R,Z,Ni (j 0..5),
    // pass2 accumulates R,Z into j 0..3 and Nh into accNh.
    unsigned long long acc[8][6];
    unsigned long long accNh[8][2];
#pragma unroll
    for (int i = 0; i < 8; ++i) {
#pragma unroll
        for (int j = 0; j < 6; ++j) acc[i][j] = 0ULL;
        accNh[i][0] = accNh[i][1] = 0ULL;
    }

    // ================= pass 1: x @ wih^T =================
    for (int k0 = 0; k0 < KIN; k0 += KC) {
        __syncthreads();
#pragma unroll
        for (int it = 0; it < 4; ++it) {            // 512 float4
            int idx = tid + 128 * it;
            int row = idx >> 3, k4 = (idx & 7) * 4;
            float4 v = *(const float4*)&xin[(size_t)(r0 + row) * KIN + k0 + k4];
            As[k4][row] = v.x; As[k4 + 1][row] = v.y;
            As[k4 + 2][row] = v.z; As[k4 + 3][row] = v.w;
        }
#pragma unroll
        for (int it = 0; it < 12; ++it) {           // 1536 float4
            int idx = tid + 128 * it;
            int c = idx >> 3, k4 = (idx & 7) * 4;
            int g = c >> 6, u = c & 63;
            float4 v = *(const float4*)&wih[(size_t)(g * HID + u0 + u) * KIN + k0 + k4];
            Ws[k4][c] = v.x; Ws[k4 + 1][c] = v.y;
            Ws[k4 + 2][c] = v.z; Ws[k4 + 3][c] = v.w;
        }
        __syncthreads();
#pragma unroll
        for (int k = 0; k < KC; ++k) {
            float4 a0 = *(const float4*)&As[k][ty * 8];
            float4 a1 = *(const float4*)&As[k][ty * 8 + 4];
            ulonglong2 w0 = *(const ulonglong2*)&Ws[k][tx * 4];
            ulonglong2 w1 = *(const ulonglong2*)&Ws[k][BU + tx * 4];
            ulonglong2 w2 = *(const ulonglong2*)&Ws[k][2 * BU + tx * 4];
            float a[8] = {a0.x, a0.y, a0.z, a0.w, a1.x, a1.y, a1.z, a1.w};
#pragma unroll
            for (int i = 0; i < 8; ++i) {
                unsigned long long ad = dup_f32(a[i]);
                ffma2(acc[i][0], ad, w0.x); ffma2(acc[i][1], ad, w0.y);
                ffma2(acc[i][2], ad, w1.x); ffma2(acc[i][3], ad, w1.y);
                ffma2(acc[i][4], ad, w2.x); ffma2(acc[i][5], ad, w2.y);
            }
        }
    }

    // ================= pass 2: h @ whh^T =================
    for (int k0 = 0; k0 < HID; k0 += KC) {
        __syncthreads();
#pragma unroll
        for (int it = 0; it < 4; ++it) {
            int idx = tid + 128 * it;
            int row = idx >> 3, k4 = (idx & 7) * 4;
            float4 v = *(const float4*)&hin[(size_t)(r0 + row) * HID + k0 + k4];
            As[k4][row] = v.x; As[k4 + 1][row] = v.y;
            As[k4 + 2][row] = v.z; As[k4 + 3][row] = v.w;
        }
#pragma unroll
        for (int it = 0; it < 12; ++it) {
            int idx = tid + 128 * it;
            int c = idx >> 3, k4 = (idx & 7) * 4;
            int g = c >> 6, u = c & 63;
            float4 v = *(const float4*)&whh[(size_t)(g * HID + u0 + u) * HID + k0 + k4];
            Ws[k4][c] = v.x; Ws[k4 + 1][c] = v.y;
            Ws[k4 + 2][c] = v.z; Ws[k4 + 3][c] = v.w;
        }
        __syncthreads();
#pragma unroll
        for (int k = 0; k < KC; ++k) {
            float4 a0 = *(const float4*)&As[k][ty * 8];
            float4 a1 = *(const float4*)&As[k][ty * 8 + 4];
            ulonglong2 w0 = *(const ulonglong2*)&Ws[k][tx * 4];
            ulonglong2 w1 = *(const ulonglong2*)&Ws[k][BU + tx * 4];
            ulonglong2 w2 = *(const ulonglong2*)&Ws[k][2 * BU + tx * 4];
            float a[8] = {a0.x, a0.y, a0.z, a0.w, a1.x, a1.y, a1.z, a1.w};
#pragma unroll
            for (int i = 0; i < 8; ++i) {
                unsigned long long ad = dup_f32(a[i]);
                ffma2(acc[i][0], ad, w0.x); ffma2(acc[i][1], ad, w0.y);
                ffma2(acc[i][2], ad, w1.x); ffma2(acc[i][3], ad, w1.y);
                ffma2(accNh[i][0], ad, w2.x); ffma2(accNh[i][1], ad, w2.y);
            }
        }
    }

    // ================= GRU elementwise combine =================
#pragma unroll
    for (int pp = 0; pp < 2; ++pp) {
#pragma unroll
        for (int half = 0; half < 2; ++half) {
            int u = u0 + tx * 4 + pp * 2 + half;
            float br  = bih[u] + bhh[u];
            float bz  = bih[HID + u] + bhh[HID + u];
            float bni = bih[2 * HID + u];
            float bnh = bhh[2 * HID + u];
#pragma unroll
            for (int i = 0; i < 8; ++i) {
                int r = r0 + ty * 8 + i;
                float vR  = half ? hi32(acc[i][pp])     : lo32(acc[i][pp]);
                float vZ  = half ? hi32(acc[i][2 + pp]) : lo32(acc[i][2 + pp]);
                float vNi = half ? hi32(acc[i][4 + pp]) : lo32(acc[i][4 + pp]);
                float vNh = half ? hi32(accNh[i][pp])   : lo32(accNh[i][pp]);
                float hold = hin[(size_t)r * HID + u];
                float rg = sigmoidf_(vR + br);
                float zg = sigmoidf_(vZ + bz);
                float ng = tanhf(vNi + bni + rg * (vNh + bnh));
                hout[(size_t)r * HID + u] = (1.0f - zg) * ng + zg * hold;
            }
        }
    }
}

// ---------------------------------------------------------------------------
// Output: logits = h2 @ out_w^T + out_b, argmax (first-index tie-break),
// embedding gather for next step. One warp per row.
// ---------------------------------------------------------------------------
__global__ void __launch_bounds__(256) out_kernel(
    int t, int p,
    const float* __restrict__ ow, const float* __restrict__ ob,
    const float* __restrict__ emb, float* __restrict__ out)
{
    __shared__ float hs[8][HID];
    const int w    = threadIdx.x >> 5;
    const int lane = threadIdx.x & 31;
    const int b    = blockIdx.x * 8 + w;

    const float* h2 = &g_h[2][p ^ 1][b][0];
    *(float4*)&hs[w][lane * 4]       = *(const float4*)&h2[lane * 4];
    *(float4*)&hs[w][128 + lane * 4] = *(const float4*)&h2[128 + lane * 4];
    __syncwarp();

    const int v1 = lane, v2 = lane + 32;
    float acc1 = ob[v1], acc2 = ob[v2];
#pragma unroll
    for (int k = 0; k < HID; k += 4) {
        float4 h4  = *(const float4*)&hs[w][k];
        float4 w14 = *(const float4*)&ow[(size_t)v1 * HID + k];
        float4 w24 = *(const float4*)&ow[(size_t)v2 * HID + k];
        acc1 += h4.x * w14.x + h4.y * w14.y + h4.z * w14.z + h4.w * w14.w;
        acc2 += h4.x * w24.x + h4.y * w24.y + h4.z * w24.z + h4.w * w24.w;
    }

    size_t off = ((size_t)b * (TT - 1) + t) * VOC;
    out[off + v1] = acc1;
    out[off + v2] = acc2;

    float bv = acc1; int bi = v1;
    if (acc2 > bv) { bv = acc2; bi = v2; }
#pragma unroll
    for (int o = 16; o; o >>= 1) {
        float ovv = __shfl_xor_sync(0xffffffffu, bv, o);
        int   oi  = __shfl_xor_sync(0xffffffffu, bi, o);
        if (ovv > bv || (ovv == bv && oi < bi)) { bv = ovv; bi = oi; }
    }

    g_x0[b][lane]      = emb[(size_t)bi * EMBD + lane];
    g_x0[b][lane + 32] = emb[(size_t)bi * EMBD + lane + 32];
}

// ---------------------------------------------------------------------------
// h0 = tanh(z @ z2h_w^T + z2h_b) scattered into g_h[l][0][b][u].
// ---------------------------------------------------------------------------
__global__ void __launch_bounds__(256) init_h_kernel(
    const float* __restrict__ z, const float* __restrict__ zw,
    const float* __restrict__ zb)
{
    constexpr int BM = 64, BN = 64, KC = 32;
    __shared__ float As[KC][BM + 4];
    __shared__ float Ws[KC][BN + 4];

    const int tid = threadIdx.x, tx = tid & 15, ty = tid >> 4;
    const int r0 = blockIdx.x * BM, j0 = blockIdx.y * BN;

    float acc[4][4] = {};
    for (int k0 = 0; k0 < ZDIM; k0 += KC) {
        __syncthreads();
#pragma unroll
        for (int it = 0; it < 2; ++it) {
            int idx = tid + 256 * it;
            int row = idx >> 3, k4 = (idx & 7) * 4;
            float4 v = *(const float4*)&z[(size_t)(r0 + row) * ZDIM + k0 + k4];
            As[k4][row] = v.x; As[k4 + 1][row] = v.y;
            As[k4 + 2][row] = v.z; As[k4 + 3][row] = v.w;
        }
#pragma unroll
        for (int it = 0; it < 2; ++it) {
            int idx = tid + 256 * it;
            int c = idx >> 3, k4 = (idx & 7) * 4;
            float4 v = *(const float4*)&zw[(size_t)(j0 + c) * ZDIM + k0 + k4];
            Ws[k4][c] = v.x; Ws[k4 + 1][c] = v.y;
            Ws[k4 + 2][c] = v.z; Ws[k4 + 3][c] = v.w;
        }
        __syncthreads();
#pragma unroll
        for (int k = 0; k < KC; ++k) {
            float4 a4 = *(const float4*)&As[k][ty * 4];
            float4 w4 = *(const float4*)&Ws[k][tx * 4];
            float a[4]  = {a4.x, a4.y, a4.z, a4.w};
            float wv[4] = {w4.x, w4.y, w4.z, w4.w};
#pragma unroll
            for (int i = 0; i < 4; ++i)
#pragma unroll
                for (int j = 0; j < 4; ++j) acc[i][j] += a[i] * wv[j];
        }
    }
#pragma unroll
    for (int j = 0; j < 4; ++j) {
        int jj = j0 + tx * 4 + j;
        int l = jj >> 8, u = jj & 255;
        float bb = zb[jj];
#pragma unroll
        for (int i = 0; i < 4; ++i) {
            int r = r0 + ty * 4 + i;
            g_h[l][0][r][u] = tanhf(acc[i][j] + bb);
        }
    }
}

// g_x0[b][:] = emb[1][:]  (start token = 1)
__global__ void init_x_kernel(const float* __restrict__ emb)
{
    int i = blockIdx.x * blockDim.x + threadIdx.x;
    if (i < BATCH * EMBD) {
        ((float*)g_x0)[i] = emb[EMBD + (i & (EMBD - 1))];
    }
}

// ---------------------------------------------------------------------------
extern "C" void kernel_launch(void* const* d_in, const int* in_sizes, int n_in,
                              void* d_out, int out_size)
{
    const float* z     = (const float*)d_in[0];
    const float* emb   = (const float*)d_in[1];
    const float* z2h_w = (const float*)d_in[2];
    const float* z2h_b = (const float*)d_in[3];
    const float* out_w = (const float*)d_in[4];
    const float* out_b = (const float*)d_in[5];
    const float* wih[NL] = {(const float*)d_in[6],  (const float*)d_in[10], (const float*)d_in[14]};
    const float* whh[NL] = {(const float*)d_in[7],  (const float*)d_in[11], (const float*)d_in[15]};
    const float* bih[NL] = {(const float*)d_in[8],  (const float*)d_in[12], (const float*)d_in[16]};
    const float* bhh[NL] = {(const float*)d_in[9],  (const float*)d_in[13], (const float*)d_in[17]};
    float* out = (float*)d_out;

    init_h_kernel<<<dim3(BATCH / 64, 768 / 64), 256>>>(z, z2h_w, z2h_b);
    init_x_kernel<<<(BATCH * EMBD + 255) / 256, 256>>>(emb);

    dim3 lgrid(BATCH / 64, HID / 64);   // 64 x 4 = 256 blocks
    for (int t = 0; t < TT - 1; ++t) {
        int p = t & 1;
        gru_layer_kernel<EMBD><<<lgrid, 128>>>(0, p, wih[0], whh[0], bih[0], bhh[0]);
        gru_layer_kernel<HID ><<<lgrid, 128>>>(1, p, wih[1], whh[1], bih[1], bhh[1]);
        gru_layer_kernel<HID ><<<lgrid, 128>>>(2, p, wih[2], whh[2], bih[2], bhh[2]);
        out_kernel<<<BATCH / 8, 256>>>(t, p, out_w, out_b, emb, out);
    }
}